// round 6
// baseline (speedup 1.0000x reference)
#include <cuda_runtime.h>
#include <cuda_bf16.h>

// Problem constants (fixed by the reference)
#define H 64
#define V 128
#define S 64
#define BATCH 256
#define L 4096
#define HSPLIT 4   // histogram split factor

// Scratch (no allocs allowed)
__device__ float d_hn[V * H];               // layernormed hidden per vocab id
__device__ float d_g[V * S];                // gate softmax per vocab id
__device__ float d_cnt[HSPLIT * BATCH * V]; // partial histograms (as float)

typedef unsigned long long u64;

__device__ __forceinline__ u64 pack2(float lo, float hi) {
    u64 r;
    asm("mov.b64 %0, {%1, %2};" : "=l"(r) : "f"(lo), "f"(hi));
    return r;
}
__device__ __forceinline__ void fma2(u64& d, u64 a, u64 b) {
    asm("fma.rn.f32x2 %0, %1, %2, %0;" : "+l"(d) : "l"(a), "l"(b));
}
__device__ __forceinline__ void unpack2(float& lo, float& hi, u64 v) {
    asm("mov.b64 {%0, %1}, %2;" : "=f"(lo), "=f"(hi) : "l"(v));
}

// ---------------------------------------------------------------------------
// Kernel 1: blocks [0,V) per-vocab precompute; blocks [V, V+4*BATCH) histogram
// quarters. 256 threads.
// ---------------------------------------------------------------------------
__global__ void prep_hist_kernel(const float* __restrict__ embed_w,
                                 const float* __restrict__ w1,
                                 const float* __restrict__ b1,
                                 const float* __restrict__ w2,
                                 const float* __restrict__ b2,
                                 const float* __restrict__ ln_g,
                                 const float* __restrict__ ln_b,
                                 const float* __restrict__ gate_w,
                                 const float* __restrict__ gate_b,
                                 const int* __restrict__ seq) {
    int t = threadIdx.x;
    int lane = t & 31;
    int warp = t >> 5;

    if (blockIdx.x < V) {
        // ---------------- precompute for vocab v ----------------
        int v = blockIdx.x;
        __shared__ float hs[H];
        __shared__ float us[2 * H];
        __shared__ float hns[H];
        __shared__ float wred[2][2];

        if (t < H) hs[t] = embed_w[v * H + t];
        __syncthreads();

        if (t < 2 * H) {
            float acc = b1[t];
#pragma unroll
            for (int k = 0; k < H; k++) acc = fmaf(hs[k], w1[k * (2 * H) + t], acc);
            us[t] = fmaxf(acc, 0.0f);
        }
        __syncthreads();

        float xval = 0.0f;
        if (t < H) {
            float acc = b2[t];
#pragma unroll
            for (int k = 0; k < 2 * H; k++) acc = fmaf(us[k], w2[k * H + t], acc);
            xval = hs[t] + acc;
            float s = xval, sq = xval * xval;
#pragma unroll
            for (int off = 16; off > 0; off >>= 1) {
                s  += __shfl_xor_sync(0xffffffffu, s, off);
                sq += __shfl_xor_sync(0xffffffffu, sq, off);
            }
            if (lane == 0) { wred[warp][0] = s; wred[warp][1] = sq; }
        }
        __syncthreads();

        if (t < H) {
            float s  = wred[0][0] + wred[1][0];
            float sq = wred[0][1] + wred[1][1];
            float mu = s * (1.0f / H);
            float var = sq * (1.0f / H) - mu * mu;
            float rstd = rsqrtf(var + 1e-5f);
            float val = (xval - mu) * rstd * ln_g[t] + ln_b[t];
            hns[t] = val;
            d_hn[v * H + t] = val;
        }
        __syncthreads();

        // gate softmax over S=64 (threads 0..63)
        if (t < S) {
            float l = gate_b[t];
#pragma unroll
            for (int k = 0; k < H; k++) l = fmaf(hns[k], gate_w[k * S + t], l);
            float m = l;
#pragma unroll
            for (int off = 16; off > 0; off >>= 1)
                m = fmaxf(m, __shfl_xor_sync(0xffffffffu, m, off));
            if (lane == 0) wred[warp][0] = m;
            __syncthreads();
            m = fmaxf(wred[0][0], wred[1][0]);
            float e = expf(l - m);
            float ssum = e;
#pragma unroll
            for (int off = 16; off > 0; off >>= 1)
                ssum += __shfl_xor_sync(0xffffffffu, ssum, off);
            if (lane == 0) wred[warp][1] = ssum;
            __syncthreads();
            float tot = wred[0][1] + wred[1][1];
            d_g[v * S + t] = e / tot;
        } else {
            __syncthreads();
            __syncthreads();
        }
    } else {
        // ---------------- histogram quarter c of batch b ----------------
        int id = blockIdx.x - V;
        int b = id >> 2;
        int c = id & 3;
        __shared__ int sub[8][V];
        for (int i = t; i < 8 * V; i += 256) ((int*)sub)[i] = 0;
        __syncthreads();

        const int4* s4 = (const int4*)(seq + b * L) + c * 256;
        int nq = (c == 3) ? 255 : 256;
        for (int i = t; i < nq; i += 256) {
            int4 x = s4[i];
            atomicAdd(&sub[warp][x.x], 1);
            atomicAdd(&sub[warp][x.y], 1);
            atomicAdd(&sub[warp][x.z], 1);
            atomicAdd(&sub[warp][x.w], 1);
        }
        if (c == 3 && t < 3) atomicAdd(&sub[warp][seq[b * L + 4092 + t]], 1);
        __syncthreads();

        if (t < V) {
            int tot = 0;
#pragma unroll
            for (int k = 0; k < 8; k++) tot += sub[k][t];
            d_cnt[(c * BATCH + b) * V + t] = (float)tot;
        }
    }
}

// ---------------------------------------------------------------------------
// Kernel 2: per-batch keys = slot_keys + sum_v c[v]*g[v] x hn[v]  (f32x2 FMAs)
// grid = BATCH, 256 threads = 4 v-groups x 64. Thread tile: 8(n) x 8(h).
// Stage ALL 128 v of cg+hn once; 1 staging barrier; merge via buffer reuse.
// Per vv per thread: 4 LDS.128 : 32 FMA2.
// ---------------------------------------------------------------------------
struct FinalSmem {
    float cs[V];
    union {
        struct {
            float scg[V][S];   // 32 KB: count-scaled gate
            float shn[V][H];   // 32 KB: hn
        } stg;
        float red[3][64][68];  // 52.2 KB: group partials (padded rows)
    } u;
    float skeys[S][H + 1];
    float sq[H];
    float sattn[S];
    float sctx[H];
    float wredA[2], wredB[2], wredC2[2];
};

__global__ void __launch_bounds__(256, 2) final_kernel(
        const int* __restrict__ seq,
        const float* __restrict__ slot_keys,
        const float* __restrict__ out_w,
        const float* __restrict__ out_b,
        float* __restrict__ out) {
    extern __shared__ char smem_raw[];
    FinalSmem* sm = (FinalSmem*)smem_raw;

    int b = blockIdx.x;
    int t = threadIdx.x;   // 0..255
    int lane = t & 31;
    int warp = t >> 5;
    int tl = t & 63;       // lane within v-group
    int grp = t >> 6;      // v-group 0..3

    // counts = sum of 4 partials
    if (t < V) {
        float c = d_cnt[(0 * BATCH + b) * V + t] + d_cnt[(1 * BATCH + b) * V + t]
                + d_cnt[(2 * BATCH + b) * V + t] + d_cnt[(3 * BATCH + b) * V + t];
        sm->cs[t] = c;
    }
    __syncthreads();

    // stage all 128 v rows of cg and hn (2048 quads each; 8+8 per thread)
#pragma unroll
    for (int idx = t; idx < 2048; idx += 256) {
        int vv = idx >> 4;
        int n4 = (idx & 15) * 4;
        float c = sm->cs[vv];
        float4 gg = *(const float4*)&d_g[vv * S + n4];
        gg.x *= c; gg.y *= c; gg.z *= c; gg.w *= c;
        *(float4*)&sm->u.stg.scg[vv][n4] = gg;
        *(float4*)&sm->u.stg.shn[vv][n4] = *(const float4*)&d_hn[vv * H + n4];
    }
    __syncthreads();

    const int n0 = (tl & 7) * 8;   // 8 slot rows
    const int h0 = (tl >> 3) * 8;  // 8 h columns

    u64 acc2[8][4];
#pragma unroll
    for (int j = 0; j < 8; j++)
#pragma unroll
        for (int i = 0; i < 4; i++) acc2[j][i] = 0ULL;

    const int vbeg = grp * 32;
#pragma unroll 4
    for (int k = 0; k < 32; k++) {
        int vv = vbeg + k;
        ulonglong2 hva = *(const ulonglong2*)&sm->u.stg.shn[vv][h0];
        ulonglong2 hvb = *(const ulonglong2*)&sm->u.stg.shn[vv][h0 + 4];
        u64 hv0 = hva.x, hv1 = hva.y, hv2v = hvb.x, hv3 = hvb.y;
        float4 ga = *(const float4*)&sm->u.stg.scg[vv][n0];
        float4 gb = *(const float4*)&sm->u.stg.scg[vv][n0 + 4];
        float gf[8] = {ga.x, ga.y, ga.z, ga.w, gb.x, gb.y, gb.z, gb.w};
#pragma unroll
        for (int j = 0; j < 8; j++) {
            u64 g2 = pack2(gf[j], gf[j]);
            fma2(acc2[j][0], g2, hv0);
            fma2(acc2[j][1], g2, hv1);
            fma2(acc2[j][2], g2, hv2v);
            fma2(acc2[j][3], g2, hv3);
        }
    }
    __syncthreads();  // all reads of staged data done; buffer reusable

    // groups 1..3 dump partials into padded reuse buffers
    if (grp != 0) {
        float (*buf)[68] = sm->u.red[grp - 1];
#pragma unroll
        for (int j = 0; j < 8; j++) {
            float f[8];
#pragma unroll
            for (int i = 0; i < 4; i++) unpack2(f[2 * i], f[2 * i + 1], acc2[j][i]);
            *(float4*)&buf[n0 + j][h0]     = make_float4(f[0], f[1], f[2], f[3]);
            *(float4*)&buf[n0 + j][h0 + 4] = make_float4(f[4], f[5], f[6], f[7]);
        }
    }
    __syncthreads();

    if (grp == 0) {
#pragma unroll
        for (int j = 0; j < 8; j++) {
            float f[8];
#pragma unroll
            for (int i = 0; i < 4; i++) unpack2(f[2 * i], f[2 * i + 1], acc2[j][i]);
            const float* r0 = &sm->u.red[0][n0 + j][h0];
            const float* r1 = &sm->u.red[1][n0 + j][h0];
            const float* r2 = &sm->u.red[2][n0 + j][h0];
            const float* sk = &slot_keys[(n0 + j) * H + h0];
#pragma unroll
            for (int i = 0; i < 8; i++)
                sm->skeys[n0 + j][h0 + i] = f[i] + r0[i] + r1[i] + r2[i] + sk[i];
        }
    }

    // q = hn[last token]; q norm (warps 0,1)
    int qi = seq[b * L + (L - 1)];
    if (t < H) {
        float qv = d_hn[qi * H + t];
        sm->sq[t] = qv;
        float s = qv * qv;
#pragma unroll
        for (int off = 16; off > 0; off >>= 1)
            s += __shfl_xor_sync(0xffffffffu, s, off);
        if (lane == 0) sm->wredA[warp] = s;
    }
    __syncthreads();

    float simv = 0.0f;
    if (t < S) {
        float qinv = rsqrtf(fmaxf(sm->wredA[0] + sm->wredA[1], 1e-24f));
        float dot = 0.0f, nk = 0.0f;
#pragma unroll
        for (int k = 0; k < H; k++) {
            float kv = sm->skeys[t][k];
            dot = fmaf(kv, sm->sq[k], dot);
            nk = fmaf(kv, kv, nk);
        }
        simv = dot * qinv / fmaxf(sqrtf(nk), 1e-12f);
        float m = simv;
#pragma unroll
        for (int off = 16; off > 0; off >>= 1)
            m = fmaxf(m, __shfl_xor_sync(0xffffffffu, m, off));
        if (lane == 0) sm->wredB[warp] = m;
    }
    __syncthreads();

    float ev = 0.0f;
    if (t < S) {
        float m = fmaxf(sm->wredB[0], sm->wredB[1]);
        ev = expf(simv - m);
        float s = ev;
#pragma unroll
        for (int off = 16; off > 0; off >>= 1)
            s += __shfl_xor_sync(0xffffffffu, s, off);
        if (lane == 0) sm->wredC2[warp] = s;
    }
    __syncthreads();

    if (t < S) sm->sattn[t] = ev / (sm->wredC2[0] + sm->wredC2[1]);
    __syncthreads();

    if (t < H) {
        float c = 0.0f;
#pragma unroll
        for (int n = 0; n < S; n++) c = fmaf(sm->sattn[n], sm->skeys[n][t], c);
        sm->sctx[t] = c;
    }
    __syncthreads();

    // out[b, j] = ctx @ out_w + out_b (threads 0..127, 1 column each)
    if (t < V) {
        float o = out_b[t];
#pragma unroll
        for (int k = 0; k < H; k++) o = fmaf(sm->sctx[k], out_w[k * V + t], o);
        out[b * V + t] = o;
    }
}

// ---------------------------------------------------------------------------
extern "C" void kernel_launch(void* const* d_in, const int* in_sizes, int n_in,
                              void* d_out, int out_size) {
    const int*   seq       = (const int*)d_in[0];
    const float* embed_w   = (const float*)d_in[1];
    const float* w1        = (const float*)d_in[2];
    const float* b1        = (const float*)d_in[3];
    const float* w2        = (const float*)d_in[4];
    const float* b2        = (const float*)d_in[5];
    const float* ln_g      = (const float*)d_in[6];
    const float* ln_b      = (const float*)d_in[7];
    const float* slot_keys = (const float*)d_in[8];
    // d_in[9] = slot_vals (unused: reference sets vals = keys)
    const float* gate_w    = (const float*)d_in[10];
    const float* gate_b    = (const float*)d_in[11];
    const float* out_w     = (const float*)d_in[12];
    const float* out_b     = (const float*)d_in[13];
    float* out = (float*)d_out;

    int smem_bytes = (int)sizeof(FinalSmem);
    cudaFuncSetAttribute(final_kernel,
                         cudaFuncAttributeMaxDynamicSharedMemorySize, smem_bytes);

    prep_hist_kernel<<<V + HSPLIT * BATCH, 256>>>(embed_w, w1, b1, w2, b2,
                                                  ln_g, ln_b, gate_w, gate_b, seq);
    final_kernel<<<BATCH, 256, smem_bytes>>>(seq, slot_keys, out_w, out_b, out);
}

// round 8
// speedup vs baseline: 1.4349x; 1.4349x over previous
#include <cuda_runtime.h>
#include <cuda_bf16.h>
#include <cstdint>

// Problem constants (fixed by the reference)
#define H 64
#define V 128
#define S 64
#define BATCH 256
#define L 4096
#define HSPLIT 4

typedef unsigned long long u64;
typedef unsigned int u32;
typedef unsigned short u16;

// Scratch (no allocs allowed)
__device__ float d_hn[V * H];                 // LN'd hidden per vocab id
__device__ float d_cnt[HSPLIT * BATCH * V];   // partial histograms (as float)
// A-fragment table: [s=64][p=64] u64 words = {hi_u32{g[2p],g[2p+1]}, lo_u32{...}}
__device__ u64 d_gT64[S * (V / 2)];

__device__ __forceinline__ void mma_bf16(float* c, u32 a0, u32 a1, u32 a2, u32 a3,
                                         u32 b0, u32 b1) {
    asm volatile(
        "mma.sync.aligned.m16n8k16.row.col.f32.bf16.bf16.f32 "
        "{%0,%1,%2,%3}, {%4,%5,%6,%7}, {%8,%9}, {%0,%1,%2,%3};"
        : "+f"(c[0]), "+f"(c[1]), "+f"(c[2]), "+f"(c[3])
        : "r"(a0), "r"(a1), "r"(a2), "r"(a3), "r"(b0), "r"(b1));
}

// ---------------------------------------------------------------------------
// Kernel 1: blocks [0,V) per-vocab precompute (writes d_hn + A-fragment table);
// blocks [V, V+4*BATCH) histogram quarters. 256 threads.
// ---------------------------------------------------------------------------
__global__ void prep_hist_kernel(const float* __restrict__ embed_w,
                                 const float* __restrict__ w1,
                                 const float* __restrict__ b1,
                                 const float* __restrict__ w2,
                                 const float* __restrict__ b2,
                                 const float* __restrict__ ln_g,
                                 const float* __restrict__ ln_b,
                                 const float* __restrict__ gate_w,
                                 const float* __restrict__ gate_b,
                                 const int* __restrict__ seq) {
    int t = threadIdx.x;
    int lane = t & 31;
    int warp = t >> 5;

    if (blockIdx.x < V) {
        int v = blockIdx.x;
        __shared__ float hs[H];
        __shared__ float us[2 * H];
        __shared__ float hns[H];
        __shared__ float wred[2][2];

        if (t < H) hs[t] = embed_w[v * H + t];
        __syncthreads();

        if (t < 2 * H) {
            float acc = b1[t];
#pragma unroll
            for (int k = 0; k < H; k++) acc = fmaf(hs[k], w1[k * (2 * H) + t], acc);
            us[t] = fmaxf(acc, 0.0f);
        }
        __syncthreads();

        float xval = 0.0f;
        if (t < H) {
            float acc = b2[t];
#pragma unroll
            for (int k = 0; k < 2 * H; k++) acc = fmaf(us[k], w2[k * H + t], acc);
            xval = hs[t] + acc;
            float s = xval, sq = xval * xval;
#pragma unroll
            for (int off = 16; off > 0; off >>= 1) {
                s  += __shfl_xor_sync(0xffffffffu, s, off);
                sq += __shfl_xor_sync(0xffffffffu, sq, off);
            }
            if (lane == 0) { wred[warp][0] = s; wred[warp][1] = sq; }
        }
        __syncthreads();

        if (t < H) {
            float s  = wred[0][0] + wred[1][0];
            float sq = wred[0][1] + wred[1][1];
            float mu = s * (1.0f / H);
            float var = sq * (1.0f / H) - mu * mu;
            float rstd = rsqrtf(var + 1e-5f);
            float val = (xval - mu) * rstd * ln_g[t] + ln_b[t];
            hns[t] = val;
            d_hn[v * H + t] = val;
        }
        __syncthreads();

        // gate softmax over S=64 (threads 0..63) + scatter into A-frag table
        if (t < S) {
            float l = gate_b[t];
#pragma unroll
            for (int k = 0; k < H; k++) l = fmaf(hns[k], gate_w[k * S + t], l);
            float m = l;
#pragma unroll
            for (int off = 16; off > 0; off >>= 1)
                m = fmaxf(m, __shfl_xor_sync(0xffffffffu, m, off));
            if (lane == 0) wred[warp][0] = m;
            __syncthreads();
            m = fmaxf(wred[0][0], wred[1][0]);
            float e = expf(l - m);
            float ssum = e;
#pragma unroll
            for (int off = 16; off > 0; off >>= 1)
                ssum += __shfl_xor_sync(0xffffffffu, ssum, off);
            if (lane == 0) wred[warp][1] = ssum;
            __syncthreads();
            float gv = e / (wred[0][1] + wred[1][1]);

            // A[s=t][k=v]: hi/lo bf16 into d_gT64[s*64 + v/2] halves
            __nv_bfloat16 hi = __float2bfloat16(gv);
            __nv_bfloat16 lo = __float2bfloat16(gv - __bfloat162float(hi));
            int s = t, p = v >> 1, e2 = v & 1;
            u16* q = (u16*)d_gT64;
            q[(s * 64 + p) * 4 + e2]     = *(u16*)&hi;   // hi u32 half
            q[(s * 64 + p) * 4 + 2 + e2] = *(u16*)&lo;   // lo u32 half
        } else {
            __syncthreads();
            __syncthreads();
        }
    } else {
        // histogram quarter c of batch b
        int id = blockIdx.x - V;
        int b = id >> 2;
        int c = id & 3;
        __shared__ int sub[8][V];
        for (int i = t; i < 8 * V; i += 256) ((int*)sub)[i] = 0;
        __syncthreads();

        const int4* s4 = (const int4*)(seq + b * L) + c * 256;
        int nq = (c == 3) ? 255 : 256;
        for (int i = t; i < nq; i += 256) {
            int4 x = s4[i];
            atomicAdd(&sub[warp][x.x], 1);
            atomicAdd(&sub[warp][x.y], 1);
            atomicAdd(&sub[warp][x.z], 1);
            atomicAdd(&sub[warp][x.w], 1);
        }
        if (c == 3 && t < 3) atomicAdd(&sub[warp][seq[b * L + 4092 + t]], 1);
        __syncthreads();

        if (t < V) {
            int tot = 0;
#pragma unroll
            for (int k = 0; k < 8; k++) tot += sub[k][t];
            d_cnt[(c * BATCH + b) * V + t] = (float)tot;
        }
    }
}

// ---------------------------------------------------------------------------
// Kernel 2 (HMMA): one batch per block, 128 threads = 4 warps = 4 m16 tiles.
// D[64s, 64h] = Gt[64,128] x B[128,64], B = cnt (.) HN, bf16 3-term split.
// B staged in smem as [p=vpair 64][68 h] of {hi,lo} u32 pairs (u64).
// ---------------------------------------------------------------------------
#define BPAD 68

struct FinalSmem {
    u64 Bint[64 * BPAD];    // 34816 B
    float skeys[S][H + 1];  // 16640 B
    float cs[V];
    float sq[H];
    float sattn[S];
    float sctx[H];
    float wA[2], wB2[2], wC[2];
};

__global__ void __launch_bounds__(128, 2) final_kernel(
        const int* __restrict__ seq,
        const float* __restrict__ slot_keys,
        const float* __restrict__ out_w,
        const float* __restrict__ out_b,
        float* __restrict__ out) {
    extern __shared__ char smraw[];
    FinalSmem* sm = (FinalSmem*)smraw;

    int b = blockIdx.x;
    int t = threadIdx.x;   // 0..127
    int lane = t & 31;
    int warp = t >> 5;
    int gid = lane >> 2;   // 0..7
    int tig = lane & 3;    // 0..3

    // counts = sum of 4 partials
    if (t < V) {
        sm->cs[t] = d_cnt[(0 * BATCH + b) * V + t] + d_cnt[(1 * BATCH + b) * V + t]
                  + d_cnt[(2 * BATCH + b) * V + t] + d_cnt[(3 * BATCH + b) * V + t];
    }
    __syncthreads();

    // Build B: entry (p, h): {bf16x2 hi, bf16x2 lo} of {cnt[2p]*hn[2p][h], cnt[2p+1]*hn[2p+1][h]}
#pragma unroll
    for (int idx = t; idx < 64 * 64; idx += 128) {
        int p = idx >> 6, h = idx & 63;
        float x0 = d_hn[(2 * p) * H + h] * sm->cs[2 * p];
        float x1 = d_hn[(2 * p + 1) * H + h] * sm->cs[2 * p + 1];
        __nv_bfloat16 h0 = __float2bfloat16(x0);
        __nv_bfloat16 h1 = __float2bfloat16(x1);
        __nv_bfloat16 l0 = __float2bfloat16(x0 - __bfloat162float(h0));
        __nv_bfloat16 l1 = __float2bfloat16(x1 - __bfloat162float(h1));
        __nv_bfloat162 hp; hp.x = h0; hp.y = h1;
        __nv_bfloat162 lp; lp.x = l0; lp.y = l1;
        u64 w = (u64)(*(u32*)&hp) | ((u64)(*(u32*)&lp) << 32);
        sm->Bint[p * BPAD + h] = w;
    }
    __syncthreads();

    // MMA mainloop: warp owns m16 tile [warp*16, warp*16+16)
    float acc[8][4];
#pragma unroll
    for (int nt = 0; nt < 8; nt++)
#pragma unroll
        for (int i = 0; i < 4; i++) acc[nt][i] = 0.0f;

    const int row0 = warp * 16 + gid;
#pragma unroll
    for (int kt = 0; kt < 8; kt++) {
        int pb = kt * 8 + tig;
        u64 A0 = d_gT64[row0 * 64 + pb];
        u64 A1 = d_gT64[(row0 + 8) * 64 + pb];
        u64 A2 = d_gT64[row0 * 64 + pb + 4];
        u64 A3 = d_gT64[(row0 + 8) * 64 + pb + 4];
        u32 aH0 = (u32)A0, aL0 = (u32)(A0 >> 32);
        u32 aH1 = (u32)A1, aL1 = (u32)(A1 >> 32);
        u32 aH2 = (u32)A2, aL2 = (u32)(A2 >> 32);
        u32 aH3 = (u32)A3, aL3 = (u32)(A3 >> 32);
#pragma unroll
        for (int nt = 0; nt < 8; nt++) {
            int h = nt * 8 + gid;
            u64 B0 = sm->Bint[pb * BPAD + h];
            u64 B1 = sm->Bint[(pb + 4) * BPAD + h];
            u32 bH0 = (u32)B0, bL0 = (u32)(B0 >> 32);
            u32 bH1 = (u32)B1, bL1 = (u32)(B1 >> 32);
            mma_bf16(acc[nt], aH0, aH1, aH2, aH3, bH0, bH1);
            mma_bf16(acc[nt], aH0, aH1, aH2, aH3, bL0, bL1);
            mma_bf16(acc[nt], aL0, aL1, aL2, aL3, bH0, bH1);
        }
    }

    // write keys (+ slot_keys) to shared
#pragma unroll
    for (int nt = 0; nt < 8; nt++) {
        int col = nt * 8 + tig * 2;
        sm->skeys[row0][col]         = acc[nt][0] + slot_keys[row0 * H + col];
        sm->skeys[row0][col + 1]     = acc[nt][1] + slot_keys[row0 * H + col + 1];
        sm->skeys[row0 + 8][col]     = acc[nt][2] + slot_keys[(row0 + 8) * H + col];
        sm->skeys[row0 + 8][col + 1] = acc[nt][3] + slot_keys[(row0 + 8) * H + col + 1];
    }

    // q = hn[last token]; q norm (warps 0,1)
    int qi = seq[b * L + (L - 1)];
    if (t < H) {
        float qv = d_hn[qi * H + t];
        sm->sq[t] = qv;
        float s = qv * qv;
#pragma unroll
        for (int off = 16; off > 0; off >>= 1)
            s += __shfl_xor_sync(0xffffffffu, s, off);
        if (lane == 0) sm->wA[warp] = s;
    }
    __syncthreads();

    float simv = 0.0f;
    if (t < S) {
        float qinv = rsqrtf(fmaxf(sm->wA[0] + sm->wA[1], 1e-24f));
        float dot = 0.0f, nk = 0.0f;
#pragma unroll
        for (int k = 0; k < H; k++) {
            float kv = sm->skeys[t][k];
            dot = fmaf(kv, sm->sq[k], dot);
            nk = fmaf(kv, kv, nk);
        }
        simv = dot * qinv / fmaxf(sqrtf(nk), 1e-12f);
        float m = simv;
#pragma unroll
        for (int off = 16; off > 0; off >>= 1)
            m = fmaxf(m, __shfl_xor_sync(0xffffffffu, m, off));
        if (lane == 0) sm->wB2[warp] = m;
    }
    __syncthreads();

    float ev = 0.0f;
    if (t < S) {
        float m = fmaxf(sm->wB2[0], sm->wB2[1]);
        ev = expf(simv - m);
        float s = ev;
#pragma unroll
        for (int off = 16; off > 0; off >>= 1)
            s += __shfl_xor_sync(0xffffffffu, s, off);
        if (lane == 0) sm->wC[warp] = s;
    }
    __syncthreads();

    if (t < S) sm->sattn[t] = ev / (sm->wC[0] + sm->wC[1]);
    __syncthreads();

    if (t < H) {
        float c = 0.0f;
#pragma unroll
        for (int n = 0; n < S; n++) c = fmaf(sm->sattn[n], sm->skeys[n][t], c);
        sm->sctx[t] = c;
    }
    __syncthreads();

    // out[b, j] = ctx @ out_w + out_b (128 threads, 1 column each)
    {
        float o = out_b[t];
#pragma unroll
        for (int k = 0; k < H; k++) o = fmaf(sm->sctx[k], out_w[k * V + t], o);
        out[b * V + t] = o;
    }
}

// ---------------------------------------------------------------------------
extern "C" void kernel_launch(void* const* d_in, const int* in_sizes, int n_in,
                              void* d_out, int out_size) {
    const int*   seq       = (const int*)d_in[0];
    const float* embed_w   = (const float*)d_in[1];
    const float* w1        = (const float*)d_in[2];
    const float* b1        = (const float*)d_in[3];
    const float* w2        = (const float*)d_in[4];
    const float* b2        = (const float*)d_in[5];
    const float* ln_g      = (const float*)d_in[6];
    const float* ln_b      = (const float*)d_in[7];
    const float* slot_keys = (const float*)d_in[8];
    // d_in[9] = slot_vals (unused: reference sets vals = keys)
    const float* gate_w    = (const float*)d_in[10];
    const float* gate_b    = (const float*)d_in[11];
    const float* out_w     = (const float*)d_in[12];
    const float* out_b     = (const float*)d_in[13];
    float* out = (float*)d_out;

    int smem_bytes = (int)sizeof(FinalSmem);
    cudaFuncSetAttribute(final_kernel,
                         cudaFuncAttributeMaxDynamicSharedMemorySize, smem_bytes);

    prep_hist_kernel<<<V + HSPLIT * BATCH, 256>>>(embed_w, w1, b1, w2, b2,
                                                  ln_g, ln_b, gate_w, gate_b, seq);
    final_kernel<<<BATCH, 128, smem_bytes>>>(seq, slot_keys, out_w, out_b, out);
}